// round 15
// baseline (speedup 1.0000x reference)
#include <cuda_runtime.h>

#define DOF 7
#define HID 30
#define TPB 128          // threads per block
#define ELEMS 2          // batch elements per thread
#define EPB (TPB * ELEMS)

typedef unsigned long long u64;

// ---------------------------------------------------------------------------
// Parameter block. HOT part (staged to SMEM): first-layer weights + fused
// 30x30 matrices. COLD part (read via broadcast LDG): vec matrices, biases,
// second layers.  w1 rows carry b1 in padding slot [7].
// ---------------------------------------------------------------------------
struct alignas(16) HotParams {
    float ld_w1[HID][8];   // [h][0..6]=w, [7]=b1
    float lo_w1[HID][8];
    float g_w1[HID][8];
    float MA[HID][32];     // [h][j]: MA[j,h] = sum_o m_w1[j,o]*ld_w2[o,h]
    float MB[HID][32];
    float CA[HID][32];     // [h][j]: sum_{o,d} c_w1[j,7o+d]*ld_w2[o,h]*ld_w1[h,d]
    float CB[HID][32];
};
struct alignas(16) ColdParams {
    float Mq[DOF][32];     // [d][j] = m_w1[j][28+d]   (qDDot path)
    float Cq[DOF][32];     // [d][j] = c_w1[j][196+d]  (qDot path)
    float mb1p[32];        // m_b1 + m_w1[:, :28] @ [ld_b2; lo_b2]
    float cb1[32];
    float w2m[HID][8];     // [j][o] transposed second layers, col 7 = 0
    float w2c[HID][8];
    float w2g[HID][8];
    float b_out[8];        // m_b2 + c_b2 + g_b2
};
struct alignas(16) Params {
    HotParams  hot;
    ColdParams cold;
};

__device__ Params d_params;

// ---------------------------------------------------------------------------
// Single merged prep kernel: block 0 -> small pieces, blocks 1..8 -> matrices
// ---------------------------------------------------------------------------
__global__ void prep_kernel(
    const float* __restrict__ ld_w1, const float* __restrict__ ld_b1,
    const float* __restrict__ ld_w2, const float* __restrict__ ld_b2,
    const float* __restrict__ lo_w1, const float* __restrict__ lo_b1,
    const float* __restrict__ lo_w2, const float* __restrict__ lo_b2,
    const float* __restrict__ g_w1,  const float* __restrict__ g_b1,
    const float* __restrict__ g_w2,  const float* __restrict__ g_b2,
    const float* __restrict__ m_w1,  const float* __restrict__ m_b1,
    const float* __restrict__ m_w2,  const float* __restrict__ m_b2,
    const float* __restrict__ c_w1,  const float* __restrict__ c_b1,
    const float* __restrict__ c_w2,  const float* __restrict__ c_b2)
{
    const int t = threadIdx.x;
    if (blockIdx.x == 0) {
        for (int h = t; h < HID; h += blockDim.x) {
            d_params.hot.ld_w1[h][7] = ld_b1[h];
            d_params.hot.lo_w1[h][7] = lo_b1[h];
            d_params.hot.g_w1[h][7]  = g_b1[h];
            d_params.cold.w2m[h][7] = 0.f;
            d_params.cold.w2c[h][7] = 0.f;
            d_params.cold.w2g[h][7] = 0.f;
            d_params.cold.cb1[h]   = c_b1[h];
            float v = m_b1[h];                   // h plays the role of j here
            for (int o = 0; o < DOF; o++) v += m_w1[h * 35 + o] * ld_b2[o];
            for (int o = 0; o < 21;  o++) v += m_w1[h * 35 + 7 + o] * lo_b2[o];
            d_params.cold.mb1p[h] = v;
        }
        if (t < 2) { d_params.cold.mb1p[30 + t] = 0.f; d_params.cold.cb1[30 + t] = 0.f; }
        for (int i = t; i < HID * DOF; i += blockDim.x) {
            int h = i / DOF, d = i % DOF;
            d_params.hot.ld_w1[h][d] = ld_w1[i];
            d_params.hot.lo_w1[h][d] = lo_w1[i];
            d_params.hot.g_w1[h][d]  = g_w1[i];
            int j = i / DOF, o = i % DOF;
            d_params.cold.w2m[j][o] = m_w2[o * HID + j];
            d_params.cold.w2c[j][o] = c_w2[o * HID + j];
            d_params.cold.w2g[j][o] = g_w2[o * HID + j];
        }
        for (int i = t; i < DOF * 32; i += blockDim.x) {
            int d = i / 32, j = i % 32;
            d_params.cold.Mq[d][j] = (j < HID) ? m_w1[j * 35 + 28 + d] : 0.f;
            d_params.cold.Cq[d][j] = (j < HID) ? c_w1[j * 203 + 196 + d] : 0.f;
        }
        if (t < 8) d_params.cold.b_out[t] = (t < DOF) ? (m_b2[t] + c_b2[t] + g_b2[t]) : 0.f;
        return;
    }

    const int i = (blockIdx.x - 1) * blockDim.x + t;
    if (i >= HID * 32) return;
    const int h = i / 32, j = i % 32;
    if (j >= HID) {
        d_params.hot.MA[h][j] = 0.f; d_params.hot.MB[h][j] = 0.f;
        d_params.hot.CA[h][j] = 0.f; d_params.hot.CB[h][j] = 0.f;
        return;
    }
    float w1ld[DOF], w1lo[DOF];
    #pragma unroll
    for (int d = 0; d < DOF; d++) { w1ld[d] = ld_w1[h * DOF + d]; w1lo[d] = lo_w1[h * DOF + d]; }

    float ma = 0.f, mb = 0.f, ca = 0.f, cb = 0.f;
    #pragma unroll
    for (int o = 0; o < DOF; o++) {
        float w2 = ld_w2[o * HID + h];
        ma += m_w1[j * 35 + o] * w2;
        float s = 0.f;
        #pragma unroll
        for (int d = 0; d < DOF; d++) s += c_w1[j * 203 + o * 7 + d] * w1ld[d];
        ca += w2 * s;
    }
    #pragma unroll
    for (int o = 0; o < 21; o++) {
        float w2 = lo_w2[o * HID + h];
        mb += m_w1[j * 35 + 7 + o] * w2;
        float s = 0.f;
        #pragma unroll
        for (int d = 0; d < DOF; d++) s += c_w1[j * 203 + (7 + o) * 7 + d] * w1lo[d];
        cb += w2 * s;
    }
    d_params.hot.MA[h][j] = ma;
    d_params.hot.MB[h][j] = mb;
    d_params.hot.CA[h][j] = ca;
    d_params.hot.CB[h][j] = cb;
}

// ---------------------------------------------------------------------------
// Packed f32x2 helpers (FFMA2: only reachable via PTX fma.rn.f32x2)
// ---------------------------------------------------------------------------
__device__ __forceinline__ u64 ffma2(u64 a, u64 b, u64 c) {
    u64 d;
    asm("fma.rn.f32x2 %0, %1, %2, %3;" : "=l"(d) : "l"(a), "l"(b), "l"(c));
    return d;
}
__device__ __forceinline__ u64 pk2(float x) {
    u64 r;
    asm("mov.b64 %0, {%1, %2};" : "=l"(r) : "f"(x), "f"(x));
    return r;
}
__device__ __forceinline__ float2 upk(u64 v) {
    float2 f;
    asm("mov.b64 {%0, %1}, %2;" : "=f"(f.x), "=f"(f.y) : "l"(v));
    return f;
}
__device__ __forceinline__ float tanhap(float x) {
    float r;
    asm("tanh.approx.f32 %0, %1;" : "=f"(r) : "f"(x));
    return r;
}
// sigmoid(z) = 0.5*tanh(0.5*z) + 0.5  (1 MUFU + 1 MUL + 1 FMA)
__device__ __forceinline__ float sigm(float z) {
    return fmaf(0.5f, tanhap(0.5f * z), 0.5f);
}
__device__ __forceinline__ float dot8(const float4 wa, const float4 wb,
                                      const float* q) {
    float p = wb.w;                       // bias in slot 7
    p = fmaf(wa.x, q[0], p); p = fmaf(wa.y, q[1], p);
    p = fmaf(wa.z, q[2], p); p = fmaf(wa.w, q[3], p);
    p = fmaf(wb.x, q[4], p); p = fmaf(wb.y, q[5], p);
    p = fmaf(wb.z, q[6], p);
    return p;
}

// z (15 pairs = 30 lanes) for both elements += s{0,1} * Mrow[0..29]
__device__ __forceinline__ void row_accum2(const float* __restrict__ Mrow,
                                           u64 s0, u64 s1, u64* z0, u64* z1)
{
    const ulonglong2* r2 = reinterpret_cast<const ulonglong2*>(Mrow);
    #pragma unroll
    for (int i = 0; i < 7; i++) {
        ulonglong2 w = r2[i];
        z0[2*i]   = ffma2(s0, w.x, z0[2*i]);
        z0[2*i+1] = ffma2(s0, w.y, z0[2*i+1]);
        z1[2*i]   = ffma2(s1, w.x, z1[2*i]);
        z1[2*i+1] = ffma2(s1, w.y, z1[2*i+1]);
    }
    u64 wl = *reinterpret_cast<const u64*>(Mrow + 28);
    z0[14] = ffma2(s0, wl, z0[14]);
    z1[14] = ffma2(s1, wl, z1[14]);
}

// z = bias + v @ Mv for both elements; bias/Mv in GLOBAL (broadcast LDG),
// v values read from SMEM staging at given base offsets.
__device__ __forceinline__ void vec_initN(const float* __restrict__ bias,
                                          const float (*__restrict__ Mv)[32],
                                          const float* __restrict__ v0,
                                          const float* __restrict__ v1,
                                          u64 z[ELEMS][15])
{
    const ulonglong2* b = reinterpret_cast<const ulonglong2*>(bias);
    #pragma unroll
    for (int i = 0; i < 7; i++) {
        ulonglong2 w = b[i];
        z[0][2*i] = w.x; z[0][2*i+1] = w.y;
        z[1][2*i] = w.x; z[1][2*i+1] = w.y;
    }
    {
        u64 bl = *reinterpret_cast<const u64*>(bias + 28);
        z[0][14] = bl; z[1][14] = bl;
    }
    #pragma unroll
    for (int d = 0; d < DOF; d++)
        row_accum2(&Mv[d][0], pk2(v0[d]), pk2(v1[d]), z[0], z[1]);
}

// z += trig(w1 @ [q;1]) @ M for both elements (w1/M in SMEM)
template <bool COS>
__device__ __forceinline__ void hidden_accumN(const float (*__restrict__ w1)[8],
                                              const float (*__restrict__ M)[32],
                                              const float* q0, const float* q1,
                                              u64 z[ELEMS][15])
{
    #pragma unroll 2
    for (int h = 0; h < HID; h++) {
        const float4 wa = *reinterpret_cast<const float4*>(&w1[h][0]);
        const float4 wb = *reinterpret_cast<const float4*>(&w1[h][4]);
        float p0 = dot8(wa, wb, q0);
        float p1 = dot8(wa, wb, q1);
        u64 s0 = pk2(COS ? __cosf(p0) : __sinf(p0));
        u64 s1 = pk2(COS ? __cosf(p1) : __sinf(p1));
        row_accum2(&M[h][0], s0, s1, z[0], z[1]);
    }
}

// acc += sigmoid(z) @ w2 for both elements (w2 in GLOBAL, broadcast LDG)
__device__ __forceinline__ void sig_outN(u64 z[ELEMS][15],
                                         const float (*__restrict__ w2)[8],
                                         u64 acc[ELEMS][4])
{
    #pragma unroll 2
    for (int p = 0; p < 15; p++) {
        const ulonglong2* r0 = reinterpret_cast<const ulonglong2*>(&w2[2*p][0]);
        const ulonglong2* r1 = reinterpret_cast<const ulonglong2*>(&w2[2*p+1][0]);
        ulonglong2 w0a = r0[0], w0b = r0[1];
        ulonglong2 w1a = r1[0], w1b = r1[1];
        #pragma unroll
        for (int e = 0; e < ELEMS; e++) {
            float2 zz = upk(z[e][p]);
            u64 a0 = pk2(sigm(zz.x));
            u64 a1 = pk2(sigm(zz.y));
            acc[e][0] = ffma2(a0, w0a.x, acc[e][0]); acc[e][1] = ffma2(a0, w0a.y, acc[e][1]);
            acc[e][2] = ffma2(a0, w0b.x, acc[e][2]); acc[e][3] = ffma2(a0, w0b.y, acc[e][3]);
            acc[e][0] = ffma2(a1, w1a.x, acc[e][0]); acc[e][1] = ffma2(a1, w1a.y, acc[e][1]);
            acc[e][2] = ffma2(a1, w1b.x, acc[e][2]); acc[e][3] = ffma2(a1, w1b.y, acc[e][3]);
        }
    }
}

// ---------------------------------------------------------------------------
// Main kernel: 2 batch elements per thread (t, t+TPB of block)
// ---------------------------------------------------------------------------
__global__ __launch_bounds__(TPB, 5) void delan_kernel(const float* __restrict__ x,
                                                       float* __restrict__ out, int B)
{
    __shared__ alignas(16) HotParams sp;
    __shared__ alignas(16) float sx[EPB * 21];   // reused as output staging
    const int t = threadIdx.x;
    const long base = (long)blockIdx.x * EPB;

    // stage HOT weights only (coalesced float4)
    {
        const float4* src = reinterpret_cast<const float4*>(&d_params.hot);
        float4* dst = reinterpret_cast<float4*>(&sp);
        constexpr int N4 = (int)(sizeof(HotParams) / 16);
        for (int i = t; i < N4; i += TPB) dst[i] = src[i];
    }
    // stage this block's x rows (coalesced float4)
    {
        const float4* gx = reinterpret_cast<const float4*>(x);
        float4* sx4 = reinterpret_cast<float4*>(sx);
        const long gbase = base * 21 / 4;
        const long gtot  = (long)B * 21 / 4;
        for (int i = t; i < EPB * 21 / 4; i += TPB)
            if (gbase + i < gtot) sx4[i] = gx[gbase + i];
    }
    __syncthreads();

    const ColdParams* __restrict__ cp = &d_params.cold;

    float q0[DOF], q1[DOF];
    #pragma unroll
    for (int d = 0; d < 7; d++) { q0[d] = sx[t * 21 + d]; q1[d] = sx[(t + TPB) * 21 + d]; }

    u64 acc[ELEMS][4];
    {
        const ulonglong2* b = reinterpret_cast<const ulonglong2*>(cp->b_out);
        ulonglong2 b0 = b[0], b1 = b[1];
        #pragma unroll
        for (int e = 0; e < ELEMS; e++) {
            acc[e][0] = b0.x; acc[e][1] = b0.y; acc[e][2] = b1.x; acc[e][3] = b1.y;
        }
    }

    // ---- g net (w1 from SMEM, w2 broadcast LDG) ----------------------------
    #pragma unroll 2
    for (int h = 0; h < HID; h++) {
        const float4 wa = *reinterpret_cast<const float4*>(&sp.g_w1[h][0]);
        const float4 wb = *reinterpret_cast<const float4*>(&sp.g_w1[h][4]);
        u64 s0 = pk2(__sinf(dot8(wa, wb, q0)));
        u64 s1 = pk2(__sinf(dot8(wa, wb, q1)));
        const ulonglong2* r = reinterpret_cast<const ulonglong2*>(&cp->w2g[h][0]);
        ulonglong2 wA = r[0], wB = r[1];
        acc[0][0] = ffma2(s0, wA.x, acc[0][0]); acc[0][1] = ffma2(s0, wA.y, acc[0][1]);
        acc[0][2] = ffma2(s0, wB.x, acc[0][2]); acc[0][3] = ffma2(s0, wB.y, acc[0][3]);
        acc[1][0] = ffma2(s1, wA.x, acc[1][0]); acc[1][1] = ffma2(s1, wA.y, acc[1][1]);
        acc[1][2] = ffma2(s1, wB.x, acc[1][2]); acc[1][3] = ffma2(s1, wB.y, acc[1][3]);
    }

    u64 z[ELEMS][15];

    // ---- m head: z = mb1p + qDDot@Mq + sin_ld@MA + sin_lo@MB ---------------
    vec_initN(cp->mb1p, cp->Mq, &sx[t * 21 + 14], &sx[(t + TPB) * 21 + 14], z);
    hidden_accumN<false>(sp.ld_w1, sp.MA, q0, q1, z);
    hidden_accumN<false>(sp.lo_w1, sp.MB, q0, q1, z);
    sig_outN(z, cp->w2m, acc);

    // ---- c head: z = c_b1 + qDot@Cq + cos_ld@CA + cos_lo@CB ----------------
    vec_initN(cp->cb1, cp->Cq, &sx[t * 21 + 7], &sx[(t + TPB) * 21 + 7], z);
    hidden_accumN<true>(sp.ld_w1, sp.CA, q0, q1, z);
    hidden_accumN<true>(sp.lo_w1, sp.CB, q0, q1, z);
    sig_outN(z, cp->w2c, acc);

    // ---- output staging (reuse sx) + coalesced store -----------------------
    __syncthreads();                 // all sx reads done before aliasing
    float* so = sx;
    #pragma unroll
    for (int e = 0; e < ELEMS; e++) {
        const int u = t + e * TPB;
        float2 a0 = upk(acc[e][0]), a1 = upk(acc[e][1]);
        float2 a2 = upk(acc[e][2]), a3 = upk(acc[e][3]);
        so[u * 7 + 0] = a0.x; so[u * 7 + 1] = a0.y;
        so[u * 7 + 2] = a1.x; so[u * 7 + 3] = a1.y;
        so[u * 7 + 4] = a2.x; so[u * 7 + 5] = a2.y;
        so[u * 7 + 6] = a3.x;
    }
    __syncthreads();
    {
        float4* go = reinterpret_cast<float4*>(out);
        const float4* so4 = reinterpret_cast<const float4*>(so);
        const long obase = base * 7 / 4;
        const long otot  = (long)B * 7 / 4;
        for (int i = t; i < EPB * 7 / 4; i += TPB)
            if (obase + i < otot) go[obase + i] = so4[i];
    }
}

// ---------------------------------------------------------------------------
extern "C" void kernel_launch(void* const* d_in, const int* in_sizes, int n_in,
                              void* d_out, int out_size)
{
    const float* x = (const float*)d_in[0];
    prep_kernel<<<9, 128>>>(
        (const float*)d_in[1],  (const float*)d_in[2],  (const float*)d_in[3],  (const float*)d_in[4],
        (const float*)d_in[5],  (const float*)d_in[6],  (const float*)d_in[7],  (const float*)d_in[8],
        (const float*)d_in[9],  (const float*)d_in[10], (const float*)d_in[11], (const float*)d_in[12],
        (const float*)d_in[13], (const float*)d_in[14], (const float*)d_in[15], (const float*)d_in[16],
        (const float*)d_in[17], (const float*)d_in[18], (const float*)d_in[19], (const float*)d_in[20]);

    const int B = in_sizes[0] / (3 * DOF);
    const int nb = (B + EPB - 1) / EPB;
    delan_kernel<<<nb, TPB>>>(x, (float*)d_out, B);
}

// round 17
// speedup vs baseline: 1.7164x; 1.7164x over previous
#include <cuda_runtime.h>

#define DOF 7
#define HID 30
#define TPB 128          // threads per block
#define ELEMS 2          // batch elements per thread
#define EPB (TPB * ELEMS)

typedef unsigned long long u64;

// ---------------------------------------------------------------------------
// Fused parameter block. w1 rows carry b1 in padding slot [7].
// ---------------------------------------------------------------------------
struct alignas(16) Params {
    float ld_w1[HID][8];   // [h][0..6]=w, [7]=b1
    float lo_w1[HID][8];
    float g_w1[HID][8];
    float MA[HID][32];     // [h][j]: MA[j,h] = sum_o m_w1[j,o]*ld_w2[o,h]
    float MB[HID][32];
    float CA[HID][32];     // [h][j]: sum_{o,d} c_w1[j,7o+d]*ld_w2[o,h]*ld_w1[h,d]
    float CB[HID][32];
    float Mq[DOF][32];     // [d][j] = m_w1[j][28+d]   (qDDot path)
    float Cq[DOF][32];     // [d][j] = c_w1[j][196+d]  (qDot path)
    float mb1p[32];        // m_b1 + m_w1[:, :28] @ [ld_b2; lo_b2]
    float cb1[32];
    float w2m[HID][8];     // [j][o] transposed second layers, col 7 = 0
    float w2c[HID][8];
    float w2g[HID][8];
    float b_out[8];        // m_b2 + c_b2 + g_b2
};

__device__ Params d_params;

// ---------------------------------------------------------------------------
// Single merged prep kernel: block 0 -> small pieces, blocks 1..8 -> matrices
// ---------------------------------------------------------------------------
__global__ void prep_kernel(
    const float* __restrict__ ld_w1, const float* __restrict__ ld_b1,
    const float* __restrict__ ld_w2, const float* __restrict__ ld_b2,
    const float* __restrict__ lo_w1, const float* __restrict__ lo_b1,
    const float* __restrict__ lo_w2, const float* __restrict__ lo_b2,
    const float* __restrict__ g_w1,  const float* __restrict__ g_b1,
    const float* __restrict__ g_w2,  const float* __restrict__ g_b2,
    const float* __restrict__ m_w1,  const float* __restrict__ m_b1,
    const float* __restrict__ m_w2,  const float* __restrict__ m_b2,
    const float* __restrict__ c_w1,  const float* __restrict__ c_b1,
    const float* __restrict__ c_w2,  const float* __restrict__ c_b2)
{
    const int t = threadIdx.x;
    if (blockIdx.x == 0) {
        for (int h = t; h < HID; h += blockDim.x) {
            d_params.ld_w1[h][7] = ld_b1[h];
            d_params.lo_w1[h][7] = lo_b1[h];
            d_params.g_w1[h][7]  = g_b1[h];
            d_params.w2m[h][7] = 0.f;
            d_params.w2c[h][7] = 0.f;
            d_params.w2g[h][7] = 0.f;
            d_params.cb1[h]   = c_b1[h];
            float v = m_b1[h];                   // h plays the role of j here
            for (int o = 0; o < DOF; o++) v += m_w1[h * 35 + o] * ld_b2[o];
            for (int o = 0; o < 21;  o++) v += m_w1[h * 35 + 7 + o] * lo_b2[o];
            d_params.mb1p[h] = v;
        }
        if (t < 2) { d_params.mb1p[30 + t] = 0.f; d_params.cb1[30 + t] = 0.f; }
        for (int i = t; i < HID * DOF; i += blockDim.x) {
            int h = i / DOF, d = i % DOF;
            d_params.ld_w1[h][d] = ld_w1[i];
            d_params.lo_w1[h][d] = lo_w1[i];
            d_params.g_w1[h][d]  = g_w1[i];
            int j = i / DOF, o = i % DOF;
            d_params.w2m[j][o] = m_w2[o * HID + j];
            d_params.w2c[j][o] = c_w2[o * HID + j];
            d_params.w2g[j][o] = g_w2[o * HID + j];
        }
        for (int i = t; i < DOF * 32; i += blockDim.x) {
            int d = i / 32, j = i % 32;
            d_params.Mq[d][j] = (j < HID) ? m_w1[j * 35 + 28 + d] : 0.f;
            d_params.Cq[d][j] = (j < HID) ? c_w1[j * 203 + 196 + d] : 0.f;
        }
        if (t < 8) d_params.b_out[t] = (t < DOF) ? (m_b2[t] + c_b2[t] + g_b2[t]) : 0.f;
        return;
    }

    const int i = (blockIdx.x - 1) * blockDim.x + t;
    if (i >= HID * 32) return;
    const int h = i / 32, j = i % 32;
    if (j >= HID) {
        d_params.MA[h][j] = 0.f; d_params.MB[h][j] = 0.f;
        d_params.CA[h][j] = 0.f; d_params.CB[h][j] = 0.f;
        return;
    }
    float w1ld[DOF], w1lo[DOF];
    #pragma unroll
    for (int d = 0; d < DOF; d++) { w1ld[d] = ld_w1[h * DOF + d]; w1lo[d] = lo_w1[h * DOF + d]; }

    float ma = 0.f, mb = 0.f, ca = 0.f, cb = 0.f;
    #pragma unroll
    for (int o = 0; o < DOF; o++) {
        float w2 = ld_w2[o * HID + h];
        ma += m_w1[j * 35 + o] * w2;
        float s = 0.f;
        #pragma unroll
        for (int d = 0; d < DOF; d++) s += c_w1[j * 203 + o * 7 + d] * w1ld[d];
        ca += w2 * s;
    }
    #pragma unroll
    for (int o = 0; o < 21; o++) {
        float w2 = lo_w2[o * HID + h];
        mb += m_w1[j * 35 + 7 + o] * w2;
        float s = 0.f;
        #pragma unroll
        for (int d = 0; d < DOF; d++) s += c_w1[j * 203 + (7 + o) * 7 + d] * w1lo[d];
        cb += w2 * s;
    }
    d_params.MA[h][j] = ma;
    d_params.MB[h][j] = mb;
    d_params.CA[h][j] = ca;
    d_params.CB[h][j] = cb;
}

// ---------------------------------------------------------------------------
// Packed f32x2 helpers (FFMA2: only reachable via PTX fma.rn.f32x2)
// ---------------------------------------------------------------------------
__device__ __forceinline__ u64 ffma2(u64 a, u64 b, u64 c) {
    u64 d;
    asm("fma.rn.f32x2 %0, %1, %2, %3;" : "=l"(d) : "l"(a), "l"(b), "l"(c));
    return d;
}
__device__ __forceinline__ u64 pk2(float x) {
    u64 r;
    asm("mov.b64 %0, {%1, %2};" : "=l"(r) : "f"(x), "f"(x));
    return r;
}
__device__ __forceinline__ float2 upk(u64 v) {
    float2 f;
    asm("mov.b64 {%0, %1}, %2;" : "=f"(f.x), "=f"(f.y) : "l"(v));
    return f;
}
__device__ __forceinline__ float tanhap(float x) {
    float r;
    asm("tanh.approx.f32 %0, %1;" : "=f"(r) : "f"(x));
    return r;
}
// sigmoid(z) = 0.5*tanh(0.5*z) + 0.5  (1 MUFU + 1 MUL + 1 FMA)
__device__ __forceinline__ float sigm(float z) {
    return fmaf(0.5f, tanhap(0.5f * z), 0.5f);
}
__device__ __forceinline__ float dot8(const float4 wa, const float4 wb,
                                      const float* q) {
    float p = wb.w;                       // bias in slot 7
    p = fmaf(wa.x, q[0], p); p = fmaf(wa.y, q[1], p);
    p = fmaf(wa.z, q[2], p); p = fmaf(wa.w, q[3], p);
    p = fmaf(wb.x, q[4], p); p = fmaf(wb.y, q[5], p);
    p = fmaf(wb.z, q[6], p);
    return p;
}

// z (15 pairs = 30 lanes) for both elements += s{0,1} * Mrow[0..29]
__device__ __forceinline__ void row_accum2(const float* __restrict__ Mrow,
                                           u64 s0, u64 s1, u64* z0, u64* z1)
{
    const ulonglong2* r2 = reinterpret_cast<const ulonglong2*>(Mrow);
    #pragma unroll
    for (int i = 0; i < 7; i++) {
        ulonglong2 w = r2[i];
        z0[2*i]   = ffma2(s0, w.x, z0[2*i]);
        z0[2*i+1] = ffma2(s0, w.y, z0[2*i+1]);
        z1[2*i]   = ffma2(s1, w.x, z1[2*i]);
        z1[2*i+1] = ffma2(s1, w.y, z1[2*i+1]);
    }
    u64 wl = *reinterpret_cast<const u64*>(Mrow + 28);
    z0[14] = ffma2(s0, wl, z0[14]);
    z1[14] = ffma2(s1, wl, z1[14]);
}

// z = bias + v @ Mv for both elements (weights loaded once)
__device__ __forceinline__ void vec_initN(const float* __restrict__ bias,
                                          const float (*__restrict__ Mv)[32],
                                          float v[ELEMS][DOF], u64 z[ELEMS][15])
{
    const ulonglong2* b = reinterpret_cast<const ulonglong2*>(bias);
    #pragma unroll
    for (int i = 0; i < 7; i++) {
        ulonglong2 w = b[i];
        #pragma unroll
        for (int e = 0; e < ELEMS; e++) { z[e][2*i] = w.x; z[e][2*i+1] = w.y; }
    }
    {
        u64 bl = *reinterpret_cast<const u64*>(bias + 28);
        #pragma unroll
        for (int e = 0; e < ELEMS; e++) z[e][14] = bl;
    }
    #pragma unroll
    for (int d = 0; d < DOF; d++)
        row_accum2(&Mv[d][0], pk2(v[0][d]), pk2(v[1][d]), z[0], z[1]);
}

// z += trig(w1 @ [q;1]) @ M for both elements
template <bool COS>
__device__ __forceinline__ void hidden_accumN(const float (*__restrict__ w1)[8],
                                              const float (*__restrict__ M)[32],
                                              const float* q0, const float* q1,
                                              u64 z[ELEMS][15])
{
    #pragma unroll 3
    for (int h = 0; h < HID; h++) {
        const float4 wa = *reinterpret_cast<const float4*>(&w1[h][0]);
        const float4 wb = *reinterpret_cast<const float4*>(&w1[h][4]);
        float p0 = dot8(wa, wb, q0);
        float p1 = dot8(wa, wb, q1);
        u64 s0 = pk2(COS ? __cosf(p0) : __sinf(p0));
        u64 s1 = pk2(COS ? __cosf(p1) : __sinf(p1));
        row_accum2(&M[h][0], s0, s1, z[0], z[1]);
    }
}

// acc += sigmoid(z) @ w2 for both elements
__device__ __forceinline__ void sig_outN(u64 z[ELEMS][15],
                                         const float (*__restrict__ w2)[8],
                                         u64 acc[ELEMS][4])
{
    #pragma unroll 3
    for (int p = 0; p < 15; p++) {
        const ulonglong2* r0 = reinterpret_cast<const ulonglong2*>(&w2[2*p][0]);
        const ulonglong2* r1 = reinterpret_cast<const ulonglong2*>(&w2[2*p+1][0]);
        ulonglong2 w0a = r0[0], w0b = r0[1];
        ulonglong2 w1a = r1[0], w1b = r1[1];
        #pragma unroll
        for (int e = 0; e < ELEMS; e++) {
            float2 zz = upk(z[e][p]);
            u64 a0 = pk2(sigm(zz.x));
            u64 a1 = pk2(sigm(zz.y));
            acc[e][0] = ffma2(a0, w0a.x, acc[e][0]); acc[e][1] = ffma2(a0, w0a.y, acc[e][1]);
            acc[e][2] = ffma2(a0, w0b.x, acc[e][2]); acc[e][3] = ffma2(a0, w0b.y, acc[e][3]);
            acc[e][0] = ffma2(a1, w1a.x, acc[e][0]); acc[e][1] = ffma2(a1, w1a.y, acc[e][1]);
            acc[e][2] = ffma2(a1, w1b.x, acc[e][2]); acc[e][3] = ffma2(a1, w1b.y, acc[e][3]);
        }
    }
}

// ---------------------------------------------------------------------------
// Main kernel: 2 batch elements per thread (t, t+TPB of block)
// ---------------------------------------------------------------------------
__global__ __launch_bounds__(TPB, 4) void delan_kernel(const float* __restrict__ x,
                                                       float* __restrict__ out, int B)
{
    __shared__ alignas(16) Params sp;
    __shared__ alignas(16) float sx[EPB * 21];   // reused as output staging
    const int t = threadIdx.x;
    const long base = (long)blockIdx.x * EPB;

    // stage fused weights (coalesced float4)
    {
        const float4* src = reinterpret_cast<const float4*>(&d_params);
        float4* dst = reinterpret_cast<float4*>(&sp);
        constexpr int N4 = (int)(sizeof(Params) / 16);
        for (int i = t; i < N4; i += TPB) dst[i] = src[i];
    }
    // stage this block's x rows (coalesced float4)
    {
        const float4* gx = reinterpret_cast<const float4*>(x);
        float4* sx4 = reinterpret_cast<float4*>(sx);
        const long gbase = base * 21 / 4;
        const long gtot  = (long)B * 21 / 4;
        for (int i = t; i < EPB * 21 / 4; i += TPB)
            if (gbase + i < gtot) sx4[i] = gx[gbase + i];
    }
    __syncthreads();

    float q0[DOF], q1[DOF];
    #pragma unroll
    for (int d = 0; d < 7; d++) { q0[d] = sx[t * 21 + d]; q1[d] = sx[(t + TPB) * 21 + d]; }

    u64 acc[ELEMS][4];
    {
        const ulonglong2* b = reinterpret_cast<const ulonglong2*>(sp.b_out);
        ulonglong2 b0 = b[0], b1 = b[1];
        #pragma unroll
        for (int e = 0; e < ELEMS; e++) {
            acc[e][0] = b0.x; acc[e][1] = b0.y; acc[e][2] = b1.x; acc[e][3] = b1.y;
        }
    }

    // ---- g net ------------------------------------------------------------
    #pragma unroll 2
    for (int h = 0; h < HID; h++) {
        const float4 wa = *reinterpret_cast<const float4*>(&sp.g_w1[h][0]);
        const float4 wb = *reinterpret_cast<const float4*>(&sp.g_w1[h][4]);
        u64 s0 = pk2(__sinf(dot8(wa, wb, q0)));
        u64 s1 = pk2(__sinf(dot8(wa, wb, q1)));
        const ulonglong2* r = reinterpret_cast<const ulonglong2*>(&sp.w2g[h][0]);
        ulonglong2 wA = r[0], wB = r[1];
        acc[0][0] = ffma2(s0, wA.x, acc[0][0]); acc[0][1] = ffma2(s0, wA.y, acc[0][1]);
        acc[0][2] = ffma2(s0, wB.x, acc[0][2]); acc[0][3] = ffma2(s0, wB.y, acc[0][3]);
        acc[1][0] = ffma2(s1, wA.x, acc[1][0]); acc[1][1] = ffma2(s1, wA.y, acc[1][1]);
        acc[1][2] = ffma2(s1, wB.x, acc[1][2]); acc[1][3] = ffma2(s1, wB.y, acc[1][3]);
    }

    u64 z[ELEMS][15];

    // ---- m head: z = mb1p + qDDot@Mq + sin_ld@MA + sin_lo@MB ---------------
    {
        float v[ELEMS][DOF];
        #pragma unroll
        for (int e = 0; e < ELEMS; e++)
            #pragma unroll
            for (int d = 0; d < 7; d++) v[e][d] = sx[(t + e * TPB) * 21 + 14 + d];
        vec_initN(sp.mb1p, sp.Mq, v, z);
    }
    hidden_accumN<false>(sp.ld_w1, sp.MA, q0, q1, z);
    hidden_accumN<false>(sp.lo_w1, sp.MB, q0, q1, z);
    sig_outN(z, sp.w2m, acc);

    // ---- c head: z = c_b1 + qDot@Cq + cos_ld@CA + cos_lo@CB ----------------
    {
        float v[ELEMS][DOF];
        #pragma unroll
        for (int e = 0; e < ELEMS; e++)
            #pragma unroll
            for (int d = 0; d < 7; d++) v[e][d] = sx[(t + e * TPB) * 21 + 7 + d];
        vec_initN(sp.cb1, sp.Cq, v, z);
    }
    hidden_accumN<true>(sp.ld_w1, sp.CA, q0, q1, z);
    hidden_accumN<true>(sp.lo_w1, sp.CB, q0, q1, z);
    sig_outN(z, sp.w2c, acc);

    // ---- output staging (reuse sx) + coalesced store -----------------------
    __syncthreads();                 // all sx reads done before aliasing
    float* so = sx;
    #pragma unroll
    for (int e = 0; e < ELEMS; e++) {
        const int u = t + e * TPB;
        float2 a0 = upk(acc[e][0]), a1 = upk(acc[e][1]);
        float2 a2 = upk(acc[e][2]), a3 = upk(acc[e][3]);
        so[u * 7 + 0] = a0.x; so[u * 7 + 1] = a0.y;
        so[u * 7 + 2] = a1.x; so[u * 7 + 3] = a1.y;
        so[u * 7 + 4] = a2.x; so[u * 7 + 5] = a2.y;
        so[u * 7 + 6] = a3.x;
    }
    __syncthreads();
    {
        float4* go = reinterpret_cast<float4*>(out);
        const float4* so4 = reinterpret_cast<const float4*>(so);
        const long obase = base * 7 / 4;
        const long otot  = (long)B * 7 / 4;
        for (int i = t; i < EPB * 7 / 4; i += TPB)
            if (obase + i < otot) go[obase + i] = so4[i];
    }
}

// ---------------------------------------------------------------------------
extern "C" void kernel_launch(void* const* d_in, const int* in_sizes, int n_in,
                              void* d_out, int out_size)
{
    const float* x = (const float*)d_in[0];
    prep_kernel<<<9, 128>>>(
        (const float*)d_in[1],  (const float*)d_in[2],  (const float*)d_in[3],  (const float*)d_in[4],
        (const float*)d_in[5],  (const float*)d_in[6],  (const float*)d_in[7],  (const float*)d_in[8],
        (const float*)d_in[9],  (const float*)d_in[10], (const float*)d_in[11], (const float*)d_in[12],
        (const float*)d_in[13], (const float*)d_in[14], (const float*)d_in[15], (const float*)d_in[16],
        (const float*)d_in[17], (const float*)d_in[18], (const float*)d_in[19], (const float*)d_in[20]);

    const int B = in_sizes[0] / (3 * DOF);
    const int nb = (B + EPB - 1) / EPB;
    delan_kernel<<<nb, TPB>>>(x, (float*)d_out, B);
}